// round 9
// baseline (speedup 1.0000x reference)
#include <cuda_runtime.h>
#include <math.h>
#include <stdint.h>

#define BB 256
#define HH 512
#define TT 512
#define STEPS 511

#define CS 8        // cluster size
#define ROWS 64     // H rows per CTA
#define BT 16       // batch elems per cluster
#define NTH 128
#define BST 18      // padded stride for sHb[k][b]

// Output layout (flattened tuple: keys, prs, hs, tm_modified), float32
#define KEYS_OFF 0
#define PRS_OFF  (BB * 2 * TT)
#define HS_OFF   (PRS_OFF + BB * 4 * TT)
#define TM_OFF   (HS_OFF + (size_t)BB * HH * TT)

// Shared layout (floats)
#define OFF_WT   0                      // [512][64] W_rec^T slice
#define OFF_HB   32768                  // [512][18] h_pre [k][b]
#define OFF_WIN  (OFF_HB + HH * BST)    // [6][64]
#define OFF_BIAS (OFF_WIN + 6 * ROWS)   // [64]
#define OFF_WK   (OFF_BIAS + ROWS)      // [2][512]
#define OFF_X    (OFF_WK + 2 * HH)      // [16][8]
#define OFF_INP  (OFF_X + BT * 8)       // [16][6]
#define OFF_KEY  (OFF_INP + BT * 6)     // [16]
#define OFF_BK   (OFF_KEY + BT)         // [2] (+pad)
#define SMEM_FLOATS (OFF_BK + 4)
#define SMEM_BYTES  (SMEM_FLOATS * 4)   // 174800 B

// h scratch in [t][b][i] layout (t=0 slab zeroed each launch)
__device__ float g_scr[(size_t)TT * BB * HH];

__device__ __forceinline__ unsigned long long pack2(float x, float y) {
    unsigned long long r;
    asm("mov.b64 %0, {%1, %2};" : "=l"(r) : "f"(x), "f"(y));
    return r;
}
__device__ __forceinline__ void unpack2(float& x, float& y, unsigned long long v) {
    asm("mov.b64 {%0, %1}, %2;" : "=f"(x), "=f"(y) : "l"(v));
}
__device__ __forceinline__ void ffma2(unsigned long long& d, unsigned long long a,
                                      unsigned long long b) {
    asm("fma.rn.f32x2 %0, %1, %2, %0;" : "+l"(d) : "l"(a), "l"(b));
}

__global__ void __cluster_dims__(CS, 1, 1) __launch_bounds__(NTH, 1)
rnn_kernel(const float* __restrict__ xin,
           const float* __restrict__ Win,  const float* __restrict__ bin,
           const float* __restrict__ Wrec, const float* __restrict__ brec,
           const float* __restrict__ Wkey, const float* __restrict__ bkey,
           float* __restrict__ out)
{
    extern __shared__ float sm[];
    float* sWt   = sm + OFF_WT;
    float* sHb   = sm + OFF_HB;
    float* sWin  = sm + OFF_WIN;
    float* sBias = sm + OFF_BIAS;
    float* sWk   = sm + OFF_WK;
    float* sX    = sm + OFF_X;
    float* sInp  = sm + OFF_INP;
    float* sKey  = sm + OFF_KEY;
    float* sBk   = sm + OFF_BK;

    const int tid  = threadIdx.x;
    const int rank = blockIdx.x & (CS - 1);
    const int cid  = blockIdx.x / CS;
    const int b0   = cid * BT;
    const int row0 = rank * ROWS;

    // ---- one-time init ----
    for (int idx = tid; idx < HH * ROWS; idx += NTH) {
        int r = idx & (ROWS - 1), k = idx >> 6;
        sWt[idx] = Wrec[(row0 + r) * HH + k];
    }
    for (int idx = tid; idx < 6 * ROWS; idx += NTH) {
        int r = idx & 63, j = idx >> 6;
        sWin[idx] = Win[(row0 + r) * 6 + j];
    }
    for (int idx = tid; idx < ROWS; idx += NTH)
        sBias[idx] = bin[row0 + idx] + brec[row0 + idx];
    for (int idx = tid; idx < 2 * HH; idx += NTH)
        sWk[idx] = Wkey[idx];
    for (int idx = tid; idx < HH * BST; idx += NTH)
        sHb[idx] = 0.f;                  // h0 = zeros
    if (tid < BT) sKey[tid] = 1.f;       // key0 = ones
    if (tid < 2)  sBk[tid]  = bkey[tid];
    __syncthreads();

    const int tb2 = (tid & 7) * 2;       // batches tb2, tb2+1
    const int tr4 = (tid >> 3) * 4;      // rows tr4..tr4+3

    // prefetch x for t=1
    const int xb = tid >> 3, xc = tid & 7;
    const size_t xbase = ((size_t)(b0 + xb) * 8 + xc) * TT;
    float xr = xin[xbase + 1];

    for (int s = 0; s < STEPS; s++) {
        const int t = s + 1;

        sX[tid] = xr;
        __syncthreads();

        if (tid < BT) {
            int b = tid;
            float kp = sKey[b];
            float a0 = sX[b * 8 + 0], a1 = sX[b * 8 + 1];
            float s0 = sX[b * 8 + 2], s1 = sX[b * 8 + 3];
            float s2 = sX[b * 8 + 4], s3 = sX[b * 8 + 5];
            float t0 = sX[b * 8 + 6], t1 = sX[b * 8 + 7];
            float m0 = s0 * kp + s2 * (1.f - kp);
            float m1 = s1 * kp + s3 * (1.f - kp);
            sInp[b * 6 + 0] = a0; sInp[b * 6 + 1] = a1;
            sInp[b * 6 + 2] = m0; sInp[b * 6 + 3] = m1;
            sInp[b * 6 + 4] = t0; sInp[b * 6 + 5] = t1;
            if (rank == 0) {
                float q0 = (t0 - a0) / (0.15f * a0); q0 *= q0; if (t0 == 0.f) q0 = 0.f;
                float q1 = (t0 - a1) / (0.15f * a1); q1 *= q1; if (t0 == 0.f) q1 = 0.f;
                float q2 = (t1 - m0) / (0.15f * m0); q2 *= q2; if (t1 == 0.f) q2 = 0.f;
                float q3 = (t1 - m1) / (0.15f * m1); q3 *= q3; if (t1 == 0.f) q3 = 0.f;
                float* p = out + PRS_OFF + (size_t)(b0 + b) * 4 * TT + t;
                p[0] = q0; p[TT] = q1; p[2 * TT] = q2; p[3 * TT] = q3;
            }
        }
        __syncthreads();

        // prefetch next x (hidden under GEMM)
        if (s + 1 < STEPS) xr = xin[xbase + t + 1];

        // ---- GEMM: packed f32x2, 4 rows x 2 batches per thread ----
        unsigned long long A00, A01, A10, A11;     // {row pair} x {batch}
        {
            float c0 = sBias[tr4 + 0], c1 = sBias[tr4 + 1];
            float c2 = sBias[tr4 + 2], c3 = sBias[tr4 + 3];
            A00 = pack2(c0, c1); A01 = A00;
            A10 = pack2(c2, c3); A11 = A10;
            #pragma unroll
            for (int j = 0; j < 6; j++) {
                ulonglong2 w = *(const ulonglong2*)(sWin + j * ROWS + tr4);
                unsigned long long h0 = pack2(sInp[tb2 * 6 + j], sInp[tb2 * 6 + j]);
                unsigned long long h1 = pack2(sInp[(tb2 + 1) * 6 + j], sInp[(tb2 + 1) * 6 + j]);
                ffma2(A00, w.x, h0); ffma2(A01, w.x, h1);
                ffma2(A10, w.y, h0); ffma2(A11, w.y, h1);
            }
            const float* Wp = sWt + tr4;
            const float* Hp = sHb + tb2;
            #pragma unroll 8
            for (int k = 0; k < HH; k++) {
                ulonglong2 w = *(const ulonglong2*)(Wp + (k << 6));
                float2 h = *(const float2*)(Hp + k * BST);
                unsigned long long h0 = pack2(h.x, h.x);
                unsigned long long h1 = pack2(h.y, h.y);
                ffma2(A00, w.x, h0); ffma2(A01, w.x, h1);
                ffma2(A10, w.y, h0); ffma2(A11, w.y, h1);
            }
        }
        {
            float r0, r1, r2, r3;
            size_t base = ((size_t)t * BB + b0 + tb2) * HH + row0 + tr4;
            unpack2(r0, r1, A00); unpack2(r2, r3, A10);
            *(float4*)(g_scr + base) =
                make_float4(tanhf(r0), tanhf(r1), tanhf(r2), tanhf(r3));
            unpack2(r0, r1, A01); unpack2(r2, r3, A11);
            *(float4*)(g_scr + base + HH) =
                make_float4(tanhf(r0), tanhf(r1), tanhf(r2), tanhf(r3));
        }

        // ---- exchange h_t across the cluster (release/acquire via barrier) ----
        asm volatile("barrier.cluster.arrive.aligned;" ::: "memory");
        asm volatile("barrier.cluster.wait.aligned;"   ::: "memory");

        // ---- reload full h_t (512 x 16) into sHb[k][b] ----
        {
            int w = tid >> 5, l = tid & 31;
            const float* src = g_scr + ((size_t)t * BB + b0) * HH;
            #pragma unroll
            for (int bb = 0; bb < 4; bb++) {
                int b = w * 4 + bb;
                const float* sb = src + b * HH;
                #pragma unroll
                for (int j = 0; j < 16; j++) {
                    int k = j * 32 + l;
                    sHb[k * BST + b] = sb[k];
                }
            }
        }
        __syncthreads();

        // ---- keys: 32 dots (16 b x 2 o), 4 lanes per dot ----
        {
            int l = tid & 3, g = tid >> 2;
            int b = g >> 1, o = g & 1;
            const float* wk = sWk + o * HH;
            float sum = 0.f;
            #pragma unroll 8
            for (int m = 0; m < HH / 4; m++) {
                int k = (m << 2) | l;
                sum = fmaf(wk[k], sHb[k * BST + b], sum);
            }
            sum += __shfl_down_sync(0xffffffffu, sum, 2);
            sum += __shfl_down_sync(0xffffffffu, sum, 1);
            if (l == 0) {
                float kv = 1.f / (1.f + expf(-(sum + sBk[o])));
                if (o == 0) sKey[b] = kv;
                if (rank == 0)
                    out[KEYS_OFF + (size_t)(b0 + b) * 2 * TT + o * TT + t] = kv;
            }
        }
        __syncthreads();
    }
}

// Zero t=0 planes (scratch slab, keys, prs) and copy tm_modified.
__global__ void misc_kernel(const float* __restrict__ xin, float* __restrict__ out)
{
    int idx = blockIdx.x * blockDim.x + threadIdx.x;
    if (idx < BB * HH) g_scr[idx] = 0.f;
    if (idx < BB * 2)  out[KEYS_OFF + (idx >> 1) * (2 * TT) + (idx & 1) * TT] = 0.f;
    if (idx < BB * 4)  out[PRS_OFF + (idx >> 2) * (4 * TT) + (idx & 3) * TT] = 0.f;
    if (idx < BB * 2 * TT) {
        int b = idx >> 10, r = idx & 1023;
        out[TM_OFF + idx] = xin[(size_t)b * 8 * TT + 6 * TT + r];
    }
}

// Transpose scratch [t][b][i] -> hs (b, i, t), 32x32 tiles, coalesced both ways.
__global__ void transpose_kernel(float* __restrict__ out)
{
    __shared__ float tile[32][33];
    int b  = blockIdx.z;
    int i0 = blockIdx.y * 32;
    int t0 = blockIdx.x * 32;
    int tx = threadIdx.x, ty = threadIdx.y;
    #pragma unroll
    for (int j = 0; j < 32; j += 8)
        tile[ty + j][tx] =
            g_scr[(size_t)(t0 + ty + j) * BB * HH + (size_t)b * HH + i0 + tx];
    __syncthreads();
    float* dst = out + HS_OFF + (size_t)b * HH * TT;
    #pragma unroll
    for (int j = 0; j < 32; j += 8)
        dst[(size_t)(i0 + ty + j) * TT + t0 + tx] = tile[tx][ty + j];
}

extern "C" void kernel_launch(void* const* d_in, const int* in_sizes, int n_in,
                              void* d_out, int out_size)
{
    const float* xin  = (const float*)d_in[0];
    const float* Win  = (const float*)d_in[1];
    const float* bin  = (const float*)d_in[2];
    const float* Wrec = (const float*)d_in[3];
    const float* brec = (const float*)d_in[4];
    const float* Wkey = (const float*)d_in[5];
    const float* bkey = (const float*)d_in[6];
    float* out = (float*)d_out;

    cudaFuncSetAttribute(rnn_kernel,
                         cudaFuncAttributeMaxDynamicSharedMemorySize, SMEM_BYTES);

    misc_kernel<<<1024, 256>>>(xin, out);
    rnn_kernel<<<(BB / BT) * CS, NTH, SMEM_BYTES>>>(xin, Win, bin, Wrec, brec,
                                                    Wkey, bkey, out);
    dim3 g(TT / 32, HH / 32, BB), blk(32, 8);
    transpose_kernel<<<g, blk>>>(out);
}